// round 1
// baseline (speedup 1.0000x reference)
#include <cuda_runtime.h>
#include <math.h>

#define BB 512
#define DD 768
#define HH 384

// Scratch (allocation-free rule: __device__ globals), 16B-aligned for float4.
__device__ __align__(16) float g_buf_h[2][BB * HH];   // hidden activations (mu, lv)
__device__ __align__(16) float g_buf_o[2][BB * DD];   // mu, logvar outputs
__device__ __align__(16) float g_Sy[DD];
__device__ __align__(16) float g_Sy2[DD];
__device__ double g_acc[2];                           // pos_sum, neg_sum

// ---------------------------------------------------------------------------
// Tiled fp32 GEMM: C[M,N] = act(A[M,K] @ W[K,N] + bias)
// STAGE 1: A = X (input), C = g_buf_h[z], act = ReLU
// STAGE 2: A = g_buf_h[z], C = g_buf_o[z], act = (z==1 ? tanh : identity)
// blockIdx.z selects the mu (z=0) / logvar (z=1) path.
// Tiles: 64x64 output per CTA, 16-deep K slices, 256 threads, 4x4 micro-tile.
// M,N multiples of 64; K multiple of 16 (512/384/768 all satisfy).
// ---------------------------------------------------------------------------
template <int M, int N, int K, int STAGE>
__global__ void __launch_bounds__(256)
mlp_gemm(const float* __restrict__ X,
         const float* __restrict__ W0, const float* __restrict__ W1,
         const float* __restrict__ bias0, const float* __restrict__ bias1)
{
    const int z = blockIdx.z;
    const float* __restrict__ A    = (STAGE == 1) ? X : g_buf_h[z];
    const float* __restrict__ W    = z ? W1 : W0;
    const float* __restrict__ bias = z ? bias1 : bias0;
    float* __restrict__ C          = (STAGE == 1) ? g_buf_h[z] : g_buf_o[z];

    __shared__ float As[16][64];
    __shared__ float Bs[16][64];

    const int tid = threadIdx.x;
    const int tx = tid & 15;        // 0..15 -> column group
    const int ty = tid >> 4;        // 0..15 -> row group
    const int rowBase = blockIdx.y * 64;
    const int colBase = blockIdx.x * 64;

    float acc[4][4] = {};

    for (int k0 = 0; k0 < K; k0 += 16) {
        // Load A tile 64x16 (transposed into As[k][m])
        {
            int r = tid >> 2;           // 0..63
            int c = (tid & 3) * 4;      // 0,4,8,12
            float4 v = *(const float4*)&A[(rowBase + r) * K + k0 + c];
            As[c + 0][r] = v.x;
            As[c + 1][r] = v.y;
            As[c + 2][r] = v.z;
            As[c + 3][r] = v.w;
        }
        // Load W tile 16x64
        {
            int r = tid >> 4;           // 0..15
            int c = (tid & 15) * 4;     // 0..60
            float4 v = *(const float4*)&W[(k0 + r) * N + colBase + c];
            *(float4*)&Bs[r][c] = v;
        }
        __syncthreads();

        #pragma unroll
        for (int kk = 0; kk < 16; kk++) {
            float4 a = *(const float4*)&As[kk][ty * 4];
            float4 b = *(const float4*)&Bs[kk][tx * 4];
            float ar[4] = {a.x, a.y, a.z, a.w};
            float br[4] = {b.x, b.y, b.z, b.w};
            #pragma unroll
            for (int m = 0; m < 4; m++)
                #pragma unroll
                for (int n = 0; n < 4; n++)
                    acc[m][n] = fmaf(ar[m], br[n], acc[m][n]);
        }
        __syncthreads();
    }

    #pragma unroll
    for (int m = 0; m < 4; m++) {
        const int row = rowBase + ty * 4 + m;
        #pragma unroll
        for (int n = 0; n < 4; n++) {
            const int col = colBase + tx * 4 + n;
            float v = acc[m][n] + bias[col];
            if (STAGE == 1) {
                v = fmaxf(v, 0.0f);
            } else {
                if (z == 1) v = tanhf(v);
            }
            C[row * N + col] = v;
        }
    }
}

// ---------------------------------------------------------------------------
// Column moments of y: Sy[d] = sum_j y[j,d], Sy2[d] = sum_j y[j,d]^2
// ---------------------------------------------------------------------------
__global__ void ystats_kernel(const float* __restrict__ y)
{
    int d = blockIdx.x * blockDim.x + threadIdx.x;
    if (d < DD) {
        float s = 0.0f, s2 = 0.0f;
        for (int j = 0; j < BB; j++) {
            float v = y[j * DD + d];
            s += v;
            s2 = fmaf(v, v, s2);
        }
        g_Sy[d] = s;
        g_Sy2[d] = s2;
    }
}

__global__ void init_acc_kernel()
{
    g_acc[0] = 0.0;
    g_acc[1] = 0.0;
}

// ---------------------------------------------------------------------------
// Final reduction over (i,d):
//   pos contribution: -(mu-y)^2 * 0.5 * iv - 0.5*lv
//   neg contribution (already summed over j analytically):
//       -0.5*iv*(Sy2[d] - 2*mu*Sy[d] + B*mu^2) - 0.5*B*lv
// ---------------------------------------------------------------------------
__global__ void __launch_bounds__(256)
reduce_kernel(const float* __restrict__ y)
{
    const int stride = gridDim.x * blockDim.x;
    double pos = 0.0, neg = 0.0;

    for (int t = blockIdx.x * blockDim.x + threadIdx.x; t < BB * DD; t += stride) {
        const int d = t % DD;
        const float mu = g_buf_o[0][t];
        const float lv = g_buf_o[1][t];
        const float iv = __expf(-lv) ;
        // use precise expf to be safe against rel-err threshold
        const float ivp = expf(-lv);
        (void)iv;
        const float yv = y[t];
        const float dm = mu - yv;
        pos += (double)(-0.5f * dm * dm * ivp - 0.5f * lv);
        const float q = g_Sy2[d] - 2.0f * mu * g_Sy[d] + (float)BB * mu * mu;
        neg += (double)(-0.5f * ivp * q - 0.5f * (float)BB * lv);
    }

    __shared__ double sp[256];
    __shared__ double sn[256];
    const int tid = threadIdx.x;
    sp[tid] = pos;
    sn[tid] = neg;
    __syncthreads();
    for (int off = 128; off > 0; off >>= 1) {
        if (tid < off) {
            sp[tid] += sp[tid + off];
            sn[tid] += sn[tid + off];
        }
        __syncthreads();
    }
    if (tid == 0) {
        atomicAdd(&g_acc[0], sp[0]);
        atomicAdd(&g_acc[1], sn[0]);
    }
}

__global__ void finalize_kernel(float* __restrict__ out)
{
    // C = log1p(exp(-20) / (B-1)) : the exact logsumexp constant
    const double Cc = log1p(exp(-20.0) / (double)(BB - 1));
    double result = g_acc[0] / (double)BB
                  - g_acc[1] / ((double)BB * (double)BB)
                  - Cc;
    out[0] = (float)result;
}

// ---------------------------------------------------------------------------
// Launch
// ---------------------------------------------------------------------------
extern "C" void kernel_launch(void* const* d_in, const int* in_sizes, int n_in,
                              void* d_out, int out_size)
{
    const float* x     = (const float*)d_in[0];
    const float* y     = (const float*)d_in[1];
    const float* mu_w1 = (const float*)d_in[2];
    const float* mu_b1 = (const float*)d_in[3];
    const float* mu_w2 = (const float*)d_in[4];
    const float* mu_b2 = (const float*)d_in[5];
    const float* lv_w1 = (const float*)d_in[6];
    const float* lv_b1 = (const float*)d_in[7];
    const float* lv_w2 = (const float*)d_in[8];
    const float* lv_b2 = (const float*)d_in[9];
    float* out = (float*)d_out;

    // Stage 1: hidden = relu(x @ w1 + b1)   (512x384, K=768), z in {mu, lv}
    mlp_gemm<BB, HH, DD, 1><<<dim3(HH / 64, BB / 64, 2), 256>>>(
        x, mu_w1, lv_w1, mu_b1, lv_b1);

    // y column moments (independent of stage 1 — tiny, runs inline)
    ystats_kernel<<<(DD + 255) / 256, 256>>>(y);
    init_acc_kernel<<<1, 1>>>();

    // Stage 2: out = hidden @ w2 + b2 (tanh on the lv path)  (512x768, K=384)
    mlp_gemm<BB, DD, HH, 2><<<dim3(DD / 64, BB / 64, 2), 256>>>(
        nullptr, mu_w2, lv_w2, mu_b2, lv_b2);

    // Closed-form reduction of positive & pairwise terms
    reduce_kernel<<<384, 256>>>(y);
    finalize_kernel<<<1, 1>>>(out);
}